// round 1
// baseline (speedup 1.0000x reference)
#include <cuda_runtime.h>

// Problem constants (fixed by the reference)
#define BNODES 8192          // B*N
#define EE     262144        // BNODES*K
#define DD     512
#define NRBF   128
#define NLAYER 4
#define KDEG   32

// ---- scratch (device globals; no cudaMalloc allowed) ----
__device__ float g_x[BNODES * DD];                 // 16 MB node features
__device__ float g_dist[EE];                       // 1 MB edge distances
__device__ float g_h[(long long)EE * DD];          // 512 MB silu(rbf@W1+b1)
__device__ float g_agg[BNODES * DD];               // 16 MB aggregated messages
__device__ float g_t[BNODES * DD];                 // 16 MB node-MLP hidden

__device__ __forceinline__ float silu_f(float v) {
    return v / (1.0f + __expf(-v));
}

// ============================================================
// Kernel 0a: x = embed[tokens]   (grid=BNODES, block=128, f4 copy)
// ============================================================
__global__ void k_gather(const int* __restrict__ tok, const float* __restrict__ emb) {
    int i = blockIdx.x;
    int t = tok[i];
    const float4* src = (const float4*)(emb + (long long)t * DD);
    float4* dst = (float4*)(g_x + (long long)i * DD);
    dst[threadIdx.x] = src[threadIdx.x];
}

// ============================================================
// Kernel 0b: per-edge distance
// ============================================================
__global__ void k_dist(const int* __restrict__ ei, const float* __restrict__ coords) {
    int e = blockIdx.x * 256 + threadIdx.x;
    int r = ei[e], c = ei[EE + e];
    float dx = coords[r * 3 + 0] - coords[c * 3 + 0];
    float dy = coords[r * 3 + 1] - coords[c * 3 + 1];
    float dz = coords[r * 3 + 2] - coords[c * 3 + 2];
    g_dist[e] = sqrtf(dx * dx + dy * dy + dz * dz);
}

// ============================================================
// Shared GEMM building blocks: 128x128 block tile, BK=16,
// 256 threads (16x16), 8x8 microtile per thread.
// As stored transposed [k][m] (132-float rows for f4-aligned pad),
// Bs stored [k][n].
// ============================================================
__device__ __forceinline__ void mma_tile(const float (*As)[132], const float (*Bs)[128],
                                         int tx, int ty, float acc[8][8]) {
#pragma unroll
    for (int k = 0; k < 16; k++) {
        float4 a0 = *(const float4*)&As[k][ty * 8];
        float4 a1 = *(const float4*)&As[k][ty * 8 + 4];
        float4 b0 = *(const float4*)&Bs[k][tx * 8];
        float4 b1 = *(const float4*)&Bs[k][tx * 8 + 4];
        float av[8] = {a0.x, a0.y, a0.z, a0.w, a1.x, a1.y, a1.z, a1.w};
        float bv[8] = {b0.x, b0.y, b0.z, b0.w, b1.x, b1.y, b1.z, b1.w};
#pragma unroll
        for (int i = 0; i < 8; i++)
#pragma unroll
            for (int j = 0; j < 8; j++)
                acc[i][j] = fmaf(av[i], bv[j], acc[i][j]);
    }
}

// Load 128x16 A tile (row-major A, row stride DD) transposed into As.
__device__ __forceinline__ void load_A(const float* __restrict__ A, int m0, int kc,
                                       int tid, float (*As)[132]) {
#pragma unroll
    for (int i = 0; i < 2; i++) {
        int q = i * 256 + tid;
        int r = q >> 2, c4 = q & 3;
        float4 v = *(const float4*)&A[(long long)(m0 + r) * DD + kc * 16 + c4 * 4];
        As[c4 * 4 + 0][r] = v.x;
        As[c4 * 4 + 1][r] = v.y;
        As[c4 * 4 + 2][r] = v.z;
        As[c4 * 4 + 3][r] = v.w;
    }
}

// Load 16x128 B tile (row-major W, row stride DD) into Bs.
__device__ __forceinline__ void load_B(const float* __restrict__ W, int n0, int kc,
                                       int tid, float (*Bs)[128]) {
#pragma unroll
    for (int i = 0; i < 2; i++) {
        int q = i * 256 + tid;
        int r = q >> 5, c4 = q & 31;
        *(float4*)&Bs[r][c4 * 4] =
            *(const float4*)&W[(long long)(kc * 16 + r) * DD + n0 + c4 * 4];
    }
}

// ============================================================
// Edge MLP layer-1: g_h = silu(rbf(dist) @ W1 + b1)
// A tile generated on the fly from dist (no rbf materialization).
// grid = (EE/128, 4)
// ============================================================
__global__ void __launch_bounds__(256) k_edge1(const float* __restrict__ W,
                                               const float* __restrict__ b) {
    __shared__ float sd[128];
    __shared__ float As[16][132];
    __shared__ float Bs[16][128];
    int tid = threadIdx.x, tx = tid & 15, ty = tid >> 4;
    int m0 = blockIdx.x * 128, n0 = blockIdx.y * 128;
    if (tid < 128) sd[tid] = g_dist[m0 + tid];
    __syncthreads();

    float acc[8][8] = {};
    const float step = 6.0f / 127.0f;   // linspace(0, CUTOFF, RBF)

#pragma unroll 1
    for (int kc = 0; kc < NRBF / 16; kc++) {
        // generate rbf A tile: As[k][m] = exp(-10*(d_m - c_{kc*16+k})^2)
#pragma unroll
        for (int i = 0; i < 8; i++) {
            int idx = i * 256 + tid;
            int m = idx & 127, k = idx >> 7;
            float c = (float)(kc * 16 + k) * step;
            float dd = sd[m] - c;
            As[k][m] = __expf(-10.0f * dd * dd);
        }
        load_B(W, n0, kc, tid, Bs);
        __syncthreads();
        mma_tile(As, Bs, tx, ty, acc);
        __syncthreads();
    }

    float bb[8];
#pragma unroll
    for (int j = 0; j < 8; j++) bb[j] = b[n0 + tx * 8 + j];
#pragma unroll
    for (int i = 0; i < 8; i++) {
        float o[8];
#pragma unroll
        for (int j = 0; j < 8; j++) o[j] = silu_f(acc[i][j] + bb[j]);
        float* dst = g_h + (long long)(m0 + ty * 8 + i) * DD + n0 + tx * 8;
        *(float4*)dst = make_float4(o[0], o[1], o[2], o[3]);
        *(float4*)(dst + 4) = make_float4(o[4], o[5], o[6], o[7]);
    }
}

// ============================================================
// Edge MLP layer-2 + message + segment-sum:
//   ef = g_h @ W2 + b2 ; msg = ef * x[col] ; agg[node] = sum over 32 edges
// Edges are contiguous groups of 32 per node -> a 128-row tile covers
// exactly 4 complete nodes; reduce in smem, NO atomics.
// grid = (EE/128, 4)
// ============================================================
__global__ void __launch_bounds__(256) k_edge2(const float* __restrict__ W,
                                               const float* __restrict__ b,
                                               const int* __restrict__ col) {
    __shared__ float As[16][132];
    __shared__ float Bs[16][128];
    __shared__ int scol[128];
    __shared__ float red[16][128];
    int tid = threadIdx.x, tx = tid & 15, ty = tid >> 4;
    int m0 = blockIdx.x * 128, n0 = blockIdx.y * 128;
    if (tid < 128) scol[tid] = col[m0 + tid];

    float acc[8][8] = {};
#pragma unroll 1
    for (int kc = 0; kc < DD / 16; kc++) {
        load_A(g_h, m0, kc, tid, As);
        load_B(W, n0, kc, tid, Bs);
        __syncthreads();
        mma_tile(As, Bs, tx, ty, acc);
        __syncthreads();
    }

    float bb[8];
#pragma unroll
    for (int j = 0; j < 8; j++) bb[j] = b[n0 + tx * 8 + j];

    // msg = ef * x[col]; partial sum over this thread's 8 consecutive rows
    float part[8] = {};
#pragma unroll
    for (int i = 0; i < 8; i++) {
        int row = ty * 8 + i;
        const float* xp = g_x + (long long)scol[row] * DD + n0 + tx * 8;
        float4 x0 = *(const float4*)xp;
        float4 x1 = *(const float4*)(xp + 4);
        float xv[8] = {x0.x, x0.y, x0.z, x0.w, x1.x, x1.y, x1.z, x1.w};
#pragma unroll
        for (int j = 0; j < 8; j++)
            part[j] = fmaf(acc[i][j] + bb[j], xv[j], part[j]);
    }
    *(float4*)&red[ty][tx * 8] = make_float4(part[0], part[1], part[2], part[3]);
    *(float4*)&red[ty][tx * 8 + 4] = make_float4(part[4], part[5], part[6], part[7]);
    __syncthreads();

    // combine 4 ty-bands (= 32 rows = one node) per group
    if ((ty & 3) == 0) {
        int g = ty >> 2;   // node within tile, 0..3
        float s[8];
#pragma unroll
        for (int j = 0; j < 8; j++) {
            s[j] = red[ty][tx * 8 + j] + red[ty + 1][tx * 8 + j] +
                   red[ty + 2][tx * 8 + j] + red[ty + 3][tx * 8 + j];
        }
        float* dst = g_agg + (long long)(blockIdx.x * 4 + g) * DD + n0 + tx * 8;
        *(float4*)dst = make_float4(s[0], s[1], s[2], s[3]);
        *(float4*)(dst + 4) = make_float4(s[4], s[5], s[6], s[7]);
    }
}

// ============================================================
// Node MLP kernels. EPI=0: g_t = silu(g_agg @ W + b)
//                   EPI=1: g_x += g_t @ W + b      (residual)
// grid = (BNODES/128, 4)
// ============================================================
template <int EPI>
__global__ void __launch_bounds__(256) k_node(const float* __restrict__ W,
                                              const float* __restrict__ b) {
    __shared__ float As[16][132];
    __shared__ float Bs[16][128];
    int tid = threadIdx.x, tx = tid & 15, ty = tid >> 4;
    int m0 = blockIdx.x * 128, n0 = blockIdx.y * 128;
    const float* A = (EPI == 0) ? g_agg : g_t;

    float acc[8][8] = {};
#pragma unroll 1
    for (int kc = 0; kc < DD / 16; kc++) {
        load_A(A, m0, kc, tid, As);
        load_B(W, n0, kc, tid, Bs);
        __syncthreads();
        mma_tile(As, Bs, tx, ty, acc);
        __syncthreads();
    }

    float bb[8];
#pragma unroll
    for (int j = 0; j < 8; j++) bb[j] = b[n0 + tx * 8 + j];
#pragma unroll
    for (int i = 0; i < 8; i++) {
        long long off = (long long)(m0 + ty * 8 + i) * DD + n0 + tx * 8;
        if (EPI == 0) {
            float o[8];
#pragma unroll
            for (int j = 0; j < 8; j++) o[j] = silu_f(acc[i][j] + bb[j]);
            *(float4*)(g_t + off) = make_float4(o[0], o[1], o[2], o[3]);
            *(float4*)(g_t + off + 4) = make_float4(o[4], o[5], o[6], o[7]);
        } else {
            float4 x0 = *(float4*)(g_x + off);
            float4 x1 = *(float4*)(g_x + off + 4);
            x0.x += acc[i][0] + bb[0];  x0.y += acc[i][1] + bb[1];
            x0.z += acc[i][2] + bb[2];  x0.w += acc[i][3] + bb[3];
            x1.x += acc[i][4] + bb[4];  x1.y += acc[i][5] + bb[5];
            x1.z += acc[i][6] + bb[6];  x1.w += acc[i][7] + bb[7];
            *(float4*)(g_x + off) = x0;
            *(float4*)(g_x + off + 4) = x1;
        }
    }
}

// ============================================================
// Output: copy g_x -> d_out; optional padding-mask tail (as 0/1 float)
// ============================================================
__global__ void k_copy_out(float* __restrict__ out) {
    long long i = (long long)blockIdx.x * 256 + threadIdx.x;  // float4 index
    ((float4*)out)[i] = ((const float4*)g_x)[i];
}

__global__ void k_mask(float* __restrict__ out, const int* __restrict__ tok, int n) {
    int i = blockIdx.x * 256 + threadIdx.x;
    if (i < n) out[i] = (i < BNODES && tok[i] == 0) ? 1.0f : 0.0f;
}

// ============================================================
extern "C" void kernel_launch(void* const* d_in, const int* in_sizes, int n_in,
                              void* d_out, int out_size) {
    const int*   tok    = (const int*)d_in[0];
    const float* coords = (const float*)d_in[1];
    const int*   ei     = (const int*)d_in[2];
    const float* emb    = (const float*)d_in[3];
    const float* ew1    = (const float*)d_in[4];
    const float* eb1    = (const float*)d_in[5];
    const float* ew2    = (const float*)d_in[6];
    const float* eb2    = (const float*)d_in[7];
    const float* nw1    = (const float*)d_in[8];
    const float* nb1    = (const float*)d_in[9];
    const float* nw2    = (const float*)d_in[10];
    const float* nb2    = (const float*)d_in[11];

    k_gather<<<BNODES, 128>>>(tok, emb);
    k_dist<<<EE / 256, 256>>>(ei, coords);

    for (int l = 0; l < NLAYER; l++) {
        k_edge1<<<dim3(EE / 128, 4), 256>>>(ew1 + (long long)l * NRBF * DD, eb1 + l * DD);
        k_edge2<<<dim3(EE / 128, 4), 256>>>(ew2 + (long long)l * DD * DD, eb2 + l * DD,
                                            ei + EE);
        k_node<0><<<dim3(BNODES / 128, 4), 256>>>(nw1 + (long long)l * DD * DD, nb1 + l * DD);
        k_node<1><<<dim3(BNODES / 128, 4), 256>>>(nw2 + (long long)l * DD * DD, nb2 + l * DD);
    }

    // encoder_rep: BNODES*DD floats, contiguous
    k_copy_out<<<(BNODES * DD) / (256 * 4), 256>>>((float*)d_out);

    int extra = out_size - BNODES * DD;   // padding_mask tail, if the harness includes it
    if (extra > 0)
        k_mask<<<(extra + 255) / 256, 256>>>((float*)d_out + BNODES * DD, tok, extra);
}

// round 3
// speedup vs baseline: 6.4585x; 6.4585x over previous
#include <cuda_runtime.h>
#include <cstdint>

// ----- problem constants -----
#define BNODES 8192
#define EE     262144
#define DD     512
#define NRBF   128
#define NLAYER 4

// ----- distance->ef lookup table -----
#define NP    16384                 // grid points (multiple of 128)
#define DMAXF 10.4f                 // > 6*sqrt(3) = 10.3923 (max possible distance)
#define HSTEP (DMAXF / (float)(NP - 1))
#define INVH  ((float)(NP - 1) / DMAXF)

// ----- device scratch (no cudaMalloc allowed) -----
__device__ float g_x[BNODES * DD];        // node features (16 MB)
__device__ float g_dist[EE];              // edge distances (1 MB)
__device__ float g_th[NP * DD];           // table hidden: silu(rbf@W1+b1) (32 MB)
__device__ float g_tab[NP * DD];          // table: ef(d) on grid (32 MB)
__device__ float g_agg[BNODES * DD];      // aggregated messages (16 MB)
__device__ float g_t[BNODES * DD];        // node-MLP hidden (16 MB)

__device__ __forceinline__ float silu_f(float v) {
    return v / (1.0f + __expf(-v));
}

// ============================================================
// x = embed[tokens]
// ============================================================
__global__ void k_gather(const int* __restrict__ tok, const float* __restrict__ emb) {
    int i = blockIdx.x;
    int t = tok[i];
    ((float4*)(g_x + (size_t)i * DD))[threadIdx.x] =
        ((const float4*)(emb + (size_t)t * DD))[threadIdx.x];
}

// ============================================================
// per-edge distance
// ============================================================
__global__ void k_dist(const int* __restrict__ ei, const float* __restrict__ coords) {
    int e = blockIdx.x * 256 + threadIdx.x;
    int r = ei[e], c = ei[EE + e];
    float dx = coords[r * 3 + 0] - coords[c * 3 + 0];
    float dy = coords[r * 3 + 1] - coords[c * 3 + 1];
    float dz = coords[r * 3 + 2] - coords[c * 3 + 2];
    g_dist[e] = sqrtf(dx * dx + dy * dy + dz * dz);
}

// ============================================================
// SIMT GEMM building blocks: 128x128 tile, BK=16, 256 thr, 8x8 microtile
// ============================================================
__device__ __forceinline__ void mma_tile(const float (*As)[132], const float (*Bs)[128],
                                         int tx, int ty, float acc[8][8]) {
#pragma unroll
    for (int k = 0; k < 16; k++) {
        float4 a0 = *(const float4*)&As[k][ty * 8];
        float4 a1 = *(const float4*)&As[k][ty * 8 + 4];
        float4 b0 = *(const float4*)&Bs[k][tx * 8];
        float4 b1 = *(const float4*)&Bs[k][tx * 8 + 4];
        float av[8] = {a0.x, a0.y, a0.z, a0.w, a1.x, a1.y, a1.z, a1.w};
        float bv[8] = {b0.x, b0.y, b0.z, b0.w, b1.x, b1.y, b1.z, b1.w};
#pragma unroll
        for (int i = 0; i < 8; i++)
#pragma unroll
            for (int j = 0; j < 8; j++)
                acc[i][j] = fmaf(av[i], bv[j], acc[i][j]);
    }
}

__device__ __forceinline__ void load_A(const float* __restrict__ A, int m0, int kc,
                                       int tid, float (*As)[132]) {
#pragma unroll
    for (int i = 0; i < 2; i++) {
        int q = i * 256 + tid;
        int r = q >> 2, c4 = q & 3;
        float4 v = *(const float4*)&A[(size_t)(m0 + r) * DD + kc * 16 + c4 * 4];
        As[c4 * 4 + 0][r] = v.x;
        As[c4 * 4 + 1][r] = v.y;
        As[c4 * 4 + 2][r] = v.z;
        As[c4 * 4 + 3][r] = v.w;
    }
}

__device__ __forceinline__ void load_B(const float* __restrict__ W, int n0, int kc,
                                       int tid, float (*Bs)[128]) {
#pragma unroll
    for (int i = 0; i < 2; i++) {
        int q = i * 256 + tid;
        int r = q >> 5, c4 = q & 31;
        *(float4*)&Bs[r][c4 * 4] =
            *(const float4*)&W[(size_t)(kc * 16 + r) * DD + n0 + c4 * 4];
    }
}

// ============================================================
// Table pass 1: g_th = silu(rbf(grid) @ W1 + b1), grid point m -> d = m*H
// grid = (NP/128, 4)
// ============================================================
__global__ void __launch_bounds__(256) k_tab1(const float* __restrict__ W,
                                              const float* __restrict__ b) {
    __shared__ float As[16][132];
    __shared__ float Bs[16][128];
    int tid = threadIdx.x, tx = tid & 15, ty = tid >> 4;
    int m0 = blockIdx.x * 128, n0 = blockIdx.y * 128;

    float acc[8][8] = {};
    const float step = 6.0f / 127.0f;   // rbf centers spacing

#pragma unroll 1
    for (int kc = 0; kc < NRBF / 16; kc++) {
#pragma unroll
        for (int i = 0; i < 8; i++) {
            int idx = i * 256 + tid;
            int m = idx & 127, k = idx >> 7;
            float d = (float)(m0 + m) * HSTEP;
            float c = (float)(kc * 16 + k) * step;
            float dd = d - c;
            As[k][m] = __expf(-10.0f * dd * dd);
        }
        load_B(W, n0, kc, tid, Bs);
        __syncthreads();
        mma_tile(As, Bs, tx, ty, acc);
        __syncthreads();
    }

    float bb[8];
#pragma unroll
    for (int j = 0; j < 8; j++) bb[j] = b[n0 + tx * 8 + j];
#pragma unroll
    for (int i = 0; i < 8; i++) {
        float o[8];
#pragma unroll
        for (int j = 0; j < 8; j++) o[j] = silu_f(acc[i][j] + bb[j]);
        float* dst = g_th + (size_t)(m0 + ty * 8 + i) * DD + n0 + tx * 8;
        *(float4*)dst = make_float4(o[0], o[1], o[2], o[3]);
        *(float4*)(dst + 4) = make_float4(o[4], o[5], o[6], o[7]);
    }
}

// ============================================================
// Generic GEMM C = A @ W + b with epilogue.
// EPI 0: g_t  = silu(g_agg @ W + b)       grid (BNODES/128, 4)
// EPI 1: g_x += g_t @ W + b  (residual)   grid (BNODES/128, 4)
// EPI 2: g_tab = g_th @ W + b             grid (NP/128, 4)
// ============================================================
template <int EPI>
__global__ void __launch_bounds__(256) k_gemm(const float* __restrict__ W,
                                              const float* __restrict__ b) {
    __shared__ float As[16][132];
    __shared__ float Bs[16][128];
    int tid = threadIdx.x, tx = tid & 15, ty = tid >> 4;
    int m0 = blockIdx.x * 128, n0 = blockIdx.y * 128;
    const float* A = (EPI == 0) ? g_agg : (EPI == 1) ? g_t : g_th;

    float acc[8][8] = {};
#pragma unroll 1
    for (int kc = 0; kc < DD / 16; kc++) {
        load_A(A, m0, kc, tid, As);
        load_B(W, n0, kc, tid, Bs);
        __syncthreads();
        mma_tile(As, Bs, tx, ty, acc);
        __syncthreads();
    }

    float bb[8];
#pragma unroll
    for (int j = 0; j < 8; j++) bb[j] = b[n0 + tx * 8 + j];
#pragma unroll
    for (int i = 0; i < 8; i++) {
        size_t off = (size_t)(m0 + ty * 8 + i) * DD + n0 + tx * 8;
        if (EPI == 0) {
            float o[8];
#pragma unroll
            for (int j = 0; j < 8; j++) o[j] = silu_f(acc[i][j] + bb[j]);
            *(float4*)(g_t + off) = make_float4(o[0], o[1], o[2], o[3]);
            *(float4*)(g_t + off + 4) = make_float4(o[4], o[5], o[6], o[7]);
        } else if (EPI == 1) {
            float4 x0 = *(float4*)(g_x + off);
            float4 x1 = *(float4*)(g_x + off + 4);
            x0.x += acc[i][0] + bb[0];  x0.y += acc[i][1] + bb[1];
            x0.z += acc[i][2] + bb[2];  x0.w += acc[i][3] + bb[3];
            x1.x += acc[i][4] + bb[4];  x1.y += acc[i][5] + bb[5];
            x1.z += acc[i][6] + bb[6];  x1.w += acc[i][7] + bb[7];
            *(float4*)(g_x + off) = x0;
            *(float4*)(g_x + off + 4) = x1;
        } else {
            float o[8];
#pragma unroll
            for (int j = 0; j < 8; j++) o[j] = acc[i][j] + bb[j];
            *(float4*)(g_tab + off) = make_float4(o[0], o[1], o[2], o[3]);
            *(float4*)(g_tab + off + 4) = make_float4(o[4], o[5], o[6], o[7]);
        }
    }
}

// ============================================================
// Edge pass: agg[node] = sum over 32 edges of lerp(tab, d_e) * x[col_e]
// One block per node (its 32 edges are contiguous). L2-resident table + x.
// ============================================================
__global__ void __launch_bounds__(256) k_agg(const int* __restrict__ col) {
    __shared__ int   scol[32];
    __shared__ int   sidx[32];
    __shared__ float sw[32];
    int node = blockIdx.x, tid = threadIdx.x;
    if (tid < 32) {
        int e = node * 32 + tid;
        scol[tid] = col[e];
        float f = g_dist[e] * INVH;
        int i = (int)f;
        if (i > NP - 2) i = NP - 2;
        sidx[tid] = i;
        sw[tid] = f - (float)i;
    }
    __syncthreads();

    int dim = tid * 2;
    float ax = 0.f, ay = 0.f;
#pragma unroll 4
    for (int e = 0; e < 32; e++) {
        size_t tbase = (size_t)sidx[e] * DD + dim;
        float2 t0 = *(const float2*)&g_tab[tbase];
        float2 t1 = *(const float2*)&g_tab[tbase + DD];
        float2 xv = *(const float2*)&g_x[(size_t)scol[e] * DD + dim];
        float w = sw[e];
        ax = fmaf(fmaf(w, t1.x - t0.x, t0.x), xv.x, ax);
        ay = fmaf(fmaf(w, t1.y - t0.y, t0.y), xv.y, ay);
    }
    *(float2*)&g_agg[(size_t)node * DD + dim] = make_float2(ax, ay);
}

// ============================================================
// output
// ============================================================
__global__ void k_copy_out(float* __restrict__ out) {
    size_t i = (size_t)blockIdx.x * 256 + threadIdx.x;
    ((float4*)out)[i] = ((const float4*)g_x)[i];
}
__global__ void k_mask(float* __restrict__ out, const int* __restrict__ tok, int n) {
    int i = blockIdx.x * 256 + threadIdx.x;
    if (i < n) out[i] = (i < BNODES && tok[i] == 0) ? 1.0f : 0.0f;
}

// ============================================================
extern "C" void kernel_launch(void* const* d_in, const int* in_sizes, int n_in,
                              void* d_out, int out_size) {
    const int*   tok    = (const int*)d_in[0];
    const float* coords = (const float*)d_in[1];
    const int*   ei     = (const int*)d_in[2];
    const float* emb    = (const float*)d_in[3];
    const float* ew1    = (const float*)d_in[4];
    const float* eb1    = (const float*)d_in[5];
    const float* ew2    = (const float*)d_in[6];
    const float* eb2    = (const float*)d_in[7];
    const float* nw1    = (const float*)d_in[8];
    const float* nb1    = (const float*)d_in[9];
    const float* nw2    = (const float*)d_in[10];
    const float* nb2    = (const float*)d_in[11];

    k_gather<<<BNODES, 128>>>(tok, emb);
    k_dist<<<EE / 256, 256>>>(ei, coords);

    const int* col = ei + EE;
    for (int l = 0; l < NLAYER; l++) {
        // build ef(d) lookup table for this layer (tiny GEMMs over the grid)
        k_tab1<<<dim3(NP / 128, 4), 256>>>(ew1 + (size_t)l * NRBF * DD, eb1 + l * DD);
        k_gemm<2><<<dim3(NP / 128, 4), 256>>>(ew2 + (size_t)l * DD * DD, eb2 + l * DD);
        // edge message + aggregation via table interpolation (no big GEMM)
        k_agg<<<BNODES, 256>>>(col);
        // node MLP
        k_gemm<0><<<dim3(BNODES / 128, 4), 256>>>(nw1 + (size_t)l * DD * DD, nb1 + l * DD);
        k_gemm<1><<<dim3(BNODES / 128, 4), 256>>>(nw2 + (size_t)l * DD * DD, nb2 + l * DD);
    }

    k_copy_out<<<(BNODES * DD) / (256 * 4), 256>>>((float*)d_out);
    int extra = out_size - BNODES * DD;
    if (extra > 0)
        k_mask<<<(extra + 255) / 256, 256>>>((float*)d_out + BNODES * DD, tok, extra);
}

// round 4
// speedup vs baseline: 9.7681x; 1.5124x over previous
#include <cuda_runtime.h>
#include <cstdint>

// ----- problem constants -----
#define BNODES 8192
#define EE     262144
#define DD     512
#define NRBF   128
#define NLAYER 4

// ----- distance->ef lookup table -----
#define NP    4096                  // grid points (multiple of 128)
#define DMAXF 10.4f                 // > 6*sqrt(3) max possible distance
#define HSTEP (DMAXF / (float)(NP - 1))
#define INVH  ((float)(NP - 1) / DMAXF)

// ----- device scratch -----
__device__ float g_x[BNODES * DD];
__device__ float g_dist[EE];
__device__ float g_th[NP * DD];           // silu(rbf@W1+b1) on grid (8 MB)
__device__ float g_tab[NP * DD];          // ef(d) on grid (8 MB)
__device__ float g_agg[BNODES * DD];
__device__ float g_t[BNODES * DD];

__device__ __forceinline__ float silu_f(float v) { return v / (1.0f + __expf(-v)); }

__device__ __forceinline__ void cp16(void* dst, const void* src) {
    uint32_t d = (uint32_t)__cvta_generic_to_shared(dst);
    asm volatile("cp.async.cg.shared.global [%0], [%1], 16;" :: "r"(d), "l"(src));
}
__device__ __forceinline__ void cp_commit() { asm volatile("cp.async.commit_group;"); }
__device__ __forceinline__ void cp_wait0() { asm volatile("cp.async.wait_group 0;" ::: "memory"); }

// ============================================================
__global__ void k_gather(const int* __restrict__ tok, const float* __restrict__ emb) {
    int i = blockIdx.x;
    int t = tok[i];
    ((float4*)(g_x + (size_t)i * DD))[threadIdx.x] =
        ((const float4*)(emb + (size_t)t * DD))[threadIdx.x];
}

__global__ void k_dist(const int* __restrict__ ei, const float* __restrict__ coords) {
    int e = blockIdx.x * 256 + threadIdx.x;
    int r = ei[e], c = ei[EE + e];
    float dx = coords[r * 3 + 0] - coords[c * 3 + 0];
    float dy = coords[r * 3 + 1] - coords[c * 3 + 1];
    float dz = coords[r * 3 + 2] - coords[c * 3 + 2];
    g_dist[e] = sqrtf(dx * dx + dy * dy + dz * dz);
}

// ============================================================
// shared GEMM microkernel pieces
// ============================================================
__device__ __forceinline__ void mma_tile(const float (*As)[132], const float (*Bs)[128],
                                         int tx, int ty, float acc[8][8]) {
#pragma unroll
    for (int k = 0; k < 16; k++) {
        float4 a0 = *(const float4*)&As[k][ty * 8];
        float4 a1 = *(const float4*)&As[k][ty * 8 + 4];
        float4 b0 = *(const float4*)&Bs[k][tx * 8];
        float4 b1 = *(const float4*)&Bs[k][tx * 8 + 4];
        float av[8] = {a0.x, a0.y, a0.z, a0.w, a1.x, a1.y, a1.z, a1.w};
        float bv[8] = {b0.x, b0.y, b0.z, b0.w, b1.x, b1.y, b1.z, b1.w};
#pragma unroll
        for (int i = 0; i < 8; i++)
#pragma unroll
            for (int j = 0; j < 8; j++)
                acc[i][j] = fmaf(av[i], bv[j], acc[i][j]);
    }
}

// A tile load (register staging, transposed STS)
__device__ __forceinline__ void ldA_regs(const float* __restrict__ A, int m0, int kc,
                                         int tid, float4* v) {
#pragma unroll
    for (int i = 0; i < 2; i++) {
        int q = i * 256 + tid;
        int r = q >> 2, c4 = q & 3;
        v[i] = *(const float4*)&A[(size_t)(m0 + r) * DD + kc * 16 + c4 * 4];
    }
}
__device__ __forceinline__ void stsA(float (*As)[132], int tid, const float4* v) {
#pragma unroll
    for (int i = 0; i < 2; i++) {
        int q = i * 256 + tid;
        int r = q >> 2, c4 = q & 3;
        As[c4 * 4 + 0][r] = v[i].x;
        As[c4 * 4 + 1][r] = v[i].y;
        As[c4 * 4 + 2][r] = v[i].z;
        As[c4 * 4 + 3][r] = v[i].w;
    }
}
// B tile: cp.async straight into smem (rows are contiguous 512B in gmem)
__device__ __forceinline__ void cpB(float (*Bs)[128], const float* __restrict__ W,
                                    int n0, int kc, int tid) {
#pragma unroll
    for (int i = 0; i < 2; i++) {
        int q = i * 256 + tid;
        int r = q >> 5, c4 = q & 31;
        cp16(&Bs[r][c4 * 4], &W[(size_t)(kc * 16 + r) * DD + n0 + c4 * 4]);
    }
}

// ============================================================
// Table pass 1: g_th = silu(rbf(grid) @ W1 + b1)   grid (NP/128, 4)
// A generated on the fly; B double-buffered via cp.async.
// ============================================================
__global__ void __launch_bounds__(256) k_tab1(const float* __restrict__ W,
                                              const float* __restrict__ b) {
    __shared__ float As[16][132];
    __shared__ float Bs[2][16][128];
    int tid = threadIdx.x, tx = tid & 15, ty = tid >> 4;
    int m0 = blockIdx.x * 128, n0 = blockIdx.y * 128;
    const float step = 6.0f / 127.0f;

    cpB(Bs[0], W, n0, 0, tid);
    cp_commit();

    float acc[8][8] = {};
#pragma unroll 1
    for (int kc = 0; kc < NRBF / 16; kc++) {
        int buf = kc & 1;
#pragma unroll
        for (int i = 0; i < 8; i++) {
            int idx = i * 256 + tid;
            int m = idx & 127, k = idx >> 7;
            float d = (float)(m0 + m) * HSTEP;
            float c = (float)(kc * 16 + k) * step;
            float dd = d - c;
            As[k][m] = __expf(-10.0f * dd * dd);
        }
        if (kc + 1 < NRBF / 16) { cpB(Bs[buf ^ 1], W, n0, kc + 1, tid); cp_commit(); }
        cp_wait0();
        __syncthreads();
        mma_tile(As, Bs[buf], tx, ty, acc);
        __syncthreads();
    }

    float bb[8];
#pragma unroll
    for (int j = 0; j < 8; j++) bb[j] = b[n0 + tx * 8 + j];
#pragma unroll
    for (int i = 0; i < 8; i++) {
        float o[8];
#pragma unroll
        for (int j = 0; j < 8; j++) o[j] = silu_f(acc[i][j] + bb[j]);
        float* dst = g_th + (size_t)(m0 + ty * 8 + i) * DD + n0 + tx * 8;
        *(float4*)dst = make_float4(o[0], o[1], o[2], o[3]);
        *(float4*)(dst + 4) = make_float4(o[4], o[5], o[6], o[7]);
    }
}

// ============================================================
// Generic double-buffered GEMM C = A @ W + b with epilogue.
// EPI 0: g_t  = silu(g_agg @ W + b)
// EPI 1: g_x += g_t @ W + b
// EPI 2: g_tab = g_th @ W + b
// ============================================================
template <int EPI>
__global__ void __launch_bounds__(256) k_gemm(const float* __restrict__ W,
                                              const float* __restrict__ b) {
    __shared__ float As[2][16][132];
    __shared__ float Bs[2][16][128];
    int tid = threadIdx.x, tx = tid & 15, ty = tid >> 4;
    int m0 = blockIdx.x * 128, n0 = blockIdx.y * 128;
    const float* A = (EPI == 0) ? g_agg : (EPI == 1) ? g_t : g_th;

    // prologue: stage chunk 0
    float4 av[2];
    ldA_regs(A, m0, 0, tid, av);
    cpB(Bs[0], W, n0, 0, tid);
    cp_commit();
    stsA(As[0], tid, av);
    cp_wait0();
    __syncthreads();

    float acc[8][8] = {};
    const int NCH = DD / 16;
#pragma unroll 1
    for (int kc = 0; kc < NCH; kc++) {
        int buf = kc & 1;
        if (kc + 1 < NCH) {
            cpB(Bs[buf ^ 1], W, n0, kc + 1, tid);
            cp_commit();
            ldA_regs(A, m0, kc + 1, tid, av);
        }
        mma_tile(As[buf], Bs[buf], tx, ty, acc);
        if (kc + 1 < NCH) stsA(As[buf ^ 1], tid, av);
        cp_wait0();
        __syncthreads();
    }

    float bb[8];
#pragma unroll
    for (int j = 0; j < 8; j++) bb[j] = b[n0 + tx * 8 + j];
#pragma unroll
    for (int i = 0; i < 8; i++) {
        size_t off = (size_t)(m0 + ty * 8 + i) * DD + n0 + tx * 8;
        if (EPI == 0) {
            float o[8];
#pragma unroll
            for (int j = 0; j < 8; j++) o[j] = silu_f(acc[i][j] + bb[j]);
            *(float4*)(g_t + off) = make_float4(o[0], o[1], o[2], o[3]);
            *(float4*)(g_t + off + 4) = make_float4(o[4], o[5], o[6], o[7]);
        } else if (EPI == 1) {
            float4 x0 = *(float4*)(g_x + off);
            float4 x1 = *(float4*)(g_x + off + 4);
            x0.x += acc[i][0] + bb[0];  x0.y += acc[i][1] + bb[1];
            x0.z += acc[i][2] + bb[2];  x0.w += acc[i][3] + bb[3];
            x1.x += acc[i][4] + bb[4];  x1.y += acc[i][5] + bb[5];
            x1.z += acc[i][6] + bb[6];  x1.w += acc[i][7] + bb[7];
            *(float4*)(g_x + off) = x0;
            *(float4*)(g_x + off + 4) = x1;
        } else {
            float o[8];
#pragma unroll
            for (int j = 0; j < 8; j++) o[j] = acc[i][j] + bb[j];
            *(float4*)(g_tab + off) = make_float4(o[0], o[1], o[2], o[3]);
            *(float4*)(g_tab + off + 4) = make_float4(o[4], o[5], o[6], o[7]);
        }
    }
}

// ============================================================
// Edge pass: agg[node] = sum_{32 edges} lerp(tab, d_e) * x[col_e]
// ============================================================
__global__ void __launch_bounds__(256) k_agg(const int* __restrict__ col) {
    __shared__ int   scol[32];
    __shared__ int   sidx[32];
    __shared__ float sw[32];
    int node = blockIdx.x, tid = threadIdx.x;
    if (tid < 32) {
        int e = node * 32 + tid;
        scol[tid] = col[e];
        float f = g_dist[e] * INVH;
        int i = (int)f;
        if (i > NP - 2) i = NP - 2;
        sidx[tid] = i;
        sw[tid] = f - (float)i;
    }
    __syncthreads();

    int dim = tid * 2;
    float ax = 0.f, ay = 0.f;
#pragma unroll 8
    for (int e = 0; e < 32; e++) {
        size_t tbase = (size_t)sidx[e] * DD + dim;
        float2 t0 = *(const float2*)&g_tab[tbase];
        float2 t1 = *(const float2*)&g_tab[tbase + DD];
        float2 xv = *(const float2*)&g_x[(size_t)scol[e] * DD + dim];
        float w = sw[e];
        ax = fmaf(fmaf(w, t1.x - t0.x, t0.x), xv.x, ax);
        ay = fmaf(fmaf(w, t1.y - t0.y, t0.y), xv.y, ay);
    }
    *(float2*)&g_agg[(size_t)node * DD + dim] = make_float2(ax, ay);
}

// ============================================================
__global__ void k_copy_out(float* __restrict__ out) {
    size_t i = (size_t)blockIdx.x * 256 + threadIdx.x;
    ((float4*)out)[i] = ((const float4*)g_x)[i];
}
__global__ void k_mask(float* __restrict__ out, const int* __restrict__ tok, int n) {
    int i = blockIdx.x * 256 + threadIdx.x;
    if (i < n) out[i] = (i < BNODES && tok[i] == 0) ? 1.0f : 0.0f;
}

// ============================================================
extern "C" void kernel_launch(void* const* d_in, const int* in_sizes, int n_in,
                              void* d_out, int out_size) {
    const int*   tok    = (const int*)d_in[0];
    const float* coords = (const float*)d_in[1];
    const int*   ei     = (const int*)d_in[2];
    const float* emb    = (const float*)d_in[3];
    const float* ew1    = (const float*)d_in[4];
    const float* eb1    = (const float*)d_in[5];
    const float* ew2    = (const float*)d_in[6];
    const float* eb2    = (const float*)d_in[7];
    const float* nw1    = (const float*)d_in[8];
    const float* nb1    = (const float*)d_in[9];
    const float* nw2    = (const float*)d_in[10];
    const float* nb2    = (const float*)d_in[11];

    k_gather<<<BNODES, 128>>>(tok, emb);
    k_dist<<<EE / 256, 256>>>(ei, coords);

    const int* col = ei + EE;
    for (int l = 0; l < NLAYER; l++) {
        k_tab1<<<dim3(NP / 128, 4), 256>>>(ew1 + (size_t)l * NRBF * DD, eb1 + l * DD);
        k_gemm<2><<<dim3(NP / 128, 4), 256>>>(ew2 + (size_t)l * DD * DD, eb2 + l * DD);
        k_agg<<<BNODES, 256>>>(col);
        k_gemm<0><<<dim3(BNODES / 128, 4), 256>>>(nw1 + (size_t)l * DD * DD, nb1 + l * DD);
        k_gemm<1><<<dim3(BNODES / 128, 4), 256>>>(nw2 + (size_t)l * DD * DD, nb2 + l * DD);
    }

    k_copy_out<<<(BNODES * DD) / (256 * 4), 256>>>((float*)d_out);
    int extra = out_size - BNODES * DD;
    if (extra > 0)
        k_mask<<<(extra + 255) / 256, 256>>>((float*)d_out + BNODES * DD, tok, extra);
}